// round 9
// baseline (speedup 1.0000x reference)
#include <cuda_runtime.h>
#include <cuda_fp16.h>
#include <cstdint>
#include <math.h>

// Problem dims (fixed by the reference)
#define BB 64
#define SS 2048
#define HH 512
#define TOK (BB * SS)   // 131072
#define NEGV -1e9f

// Scratch (allocations are banned; use device globals)
__device__ float g_scores[TOK];
__device__ float g_attn_fallback[TOK];
__device__ float g_part[8 * BB * HH];
__device__ int   g_mask_is_i32;
__device__ __half g_wh[HH * HH];
__device__ __half g_wl[HH * HH];

// ===========================================================================
// Helpers
// ===========================================================================
__device__ __forceinline__ uint32_t smem_u32(const void* p) {
    uint32_t a;
    asm("{ .reg .u64 t; cvta.to.shared.u64 t, %1; cvt.u32.u64 %0, t; }"
        : "=r"(a) : "l"(p));
    return a;
}
__device__ __forceinline__ void ldsm4(uint32_t (&r)[4], uint32_t addr) {
    asm volatile("ldmatrix.sync.aligned.m8n8.x4.shared.b16 {%0,%1,%2,%3}, [%4];"
        : "=r"(r[0]), "=r"(r[1]), "=r"(r[2]), "=r"(r[3]) : "r"(addr));
}
// fp16 in, fp32 accum
__device__ __forceinline__ void mma_f32(float (&c)[4], const uint32_t (&a)[4],
                                        uint32_t b0, uint32_t b1) {
    asm volatile("mma.sync.aligned.m16n8k16.row.col.f32.f16.f16.f32 "
        "{%0,%1,%2,%3}, {%4,%5,%6,%7}, {%8,%9}, {%0,%1,%2,%3};"
        : "+f"(c[0]), "+f"(c[1]), "+f"(c[2]), "+f"(c[3])
        : "r"(a[0]), "r"(a[1]), "r"(a[2]), "r"(a[3]), "r"(b0), "r"(b1));
}
// fp16 in, fp16 accum
__device__ __forceinline__ void mma_f16(uint32_t (&c)[2], const uint32_t (&a)[4],
                                        uint32_t b0, uint32_t b1) {
    asm volatile("mma.sync.aligned.m16n8k16.row.col.f16.f16.f16.f16 "
        "{%0,%1}, {%2,%3,%4,%5}, {%6,%7}, {%0,%1};"
        : "+r"(c[0]), "+r"(c[1])
        : "r"(a[0]), "r"(a[1]), "r"(a[2]), "r"(a[3]), "r"(b0), "r"(b1));
}
__device__ __forceinline__ void cp16(uint32_t dst, const void* src) {
    asm volatile("cp.async.cg.shared.global [%0], [%1], 16;"
        :: "r"(dst), "l"(src));
}
#define CP_COMMIT() asm volatile("cp.async.commit_group;" ::: "memory")
#define CP_WAIT0()  asm volatile("cp.async.wait_group 0;" ::: "memory")

__device__ __forceinline__ float fast_tanh(float x) {
    x = fminf(15.f, fmaxf(-15.f, x));
    float e = __expf(2.f * x);
    return __fdividef(e - 1.f, e + 1.f);
}

// ===========================================================================
// W pre-split: W fp32 -> Wh, Wl fp16 (global, done once per launch)
// ===========================================================================
__global__ __launch_bounds__(256)
void wsplit_kernel(const float* __restrict__ W,
                   __half* __restrict__ wh,
                   __half* __restrict__ wl)
{
    int idx = blockIdx.x * 256 + threadIdx.x;
#pragma unroll
    for (int j = 0; j < 4; j++) {
        int i = idx * 4 + j;
        float x = W[i];
        __half h = __float2half_rn(x);
        wh[i] = h;
        wl[i] = __float2half_rn(x - __half2float(h));
    }
}

// Tiny no-op so scores_tc lands at ncu's captured launch index (3).
__global__ void dummy_kernel() {}

// ===========================================================================
// Scores kernel: 3-term fp16 split GEMM + fused v.tanh(.+b) epilogue.
// Block = 256 thr (8 warps: 2 warp_m x 4 warp_n), warp tile m32 x n32.
// Per k16: 8 ldsm serve 24 MMAs (171 B/MMA shared traffic).
// Register budget forced to 128 via __launch_bounds__(256, 2) so ptxas
// cannot hoist-and-spill (R6/R8 both hit 255 regs without it).
// M-tile 64, K=512 resident A, N-chunks of 128, B via cp.async, BK=64.
// ===========================================================================
#define ASTR_A 1040             // 512 fp16 + 8 pad, bytes
#define ASTR_B 144              // 64 fp16 + 8 pad, bytes
#define A_TILE_SZ (64 * ASTR_A) // 66560
#define B_TILE_SZ (128 * ASTR_B)// 18432
#define OFF_V    0
#define OFF_BI   2048
#define OFF_RED  4096           // 64 x 16 floats
#define OFF_AH   8192
#define OFF_AL   (OFF_AH + A_TILE_SZ)      // 74752
#define OFF_B    (OFF_AL + A_TILE_SZ)      // 141312
#define BUF_SZ   (2 * B_TILE_SZ)           // hi + lo
#define SMEM_TOTAL (OFF_B + 2 * BUF_SZ)    // 215040

#define NTHR 256

__device__ __forceinline__ void issue_b(const __half* __restrict__ wh,
                                        const __half* __restrict__ wl,
                                        uint32_t dst_hi, int nc, int kt, int tid)
{
#pragma unroll
    for (int j = 0; j < 4; j++) {
        int idx = tid + j * NTHR;         // 0..1023
        int row = idx >> 3;               // n row 0..127
        int c16 = idx & 7;                // 16B chunk in k
        uint32_t d = dst_hi + row * ASTR_B + c16 * 16;
        size_t g = (size_t)(nc * 128 + row) * HH + kt * 64 + c16 * 8;
        cp16(d, wh + g);
        cp16(d + B_TILE_SZ, wl + g);
    }
    CP_COMMIT();
}

__global__ __launch_bounds__(NTHR, 2)
void scores_tc_kernel(const float* __restrict__ X,
                      const __half* __restrict__ wh,
                      const __half* __restrict__ wl,
                      const float* __restrict__ bias,
                      const float* __restrict__ v,
                      float* __restrict__ scores)
{
    extern __shared__ char smem[];
    const int tid  = threadIdx.x;
    const int lane = tid & 31;
    const int wid  = tid >> 5;
    const int warp_m = wid & 1;        // 0..1 -> 32-row slab
    const int warp_n = wid >> 1;       // 0..3 -> 32-col slab
    const int row0 = blockIdx.x * 64;

    const uint32_t sb = smem_u32(smem);
    float* sv  = (float*)(smem + OFF_V);
    float* sbi = (float*)(smem + OFF_BI);
    float* red = (float*)(smem + OFF_RED);
    for (int i = tid; i < HH; i += NTHR) { sv[i] = v[i]; sbi[i] = bias[i]; }

    // Prefetch first B tile.
    issue_b(wh, wl, sb + OFF_B, 0, 0, tid);

    // Convert A (64 x 512) fp32 -> fp16 hi/lo resident tiles, once.
    {
        char* ah = smem + OFF_AH;
        char* al = smem + OFF_AL;
#pragma unroll
        for (int j = 0; j < 32; j++) {
            int idx = tid + j * NTHR;         // 0..8191 float4s
            int r  = idx >> 7;                // row 0..63
            int c4 = (idx & 127) * 4;         // col
            float4 f = *(const float4*)(X + (size_t)(row0 + r) * HH + c4);
            __half h0 = __float2half_rn(f.x);
            __half h1 = __float2half_rn(f.y);
            __half h2 = __float2half_rn(f.z);
            __half h3 = __float2half_rn(f.w);
            uint32_t hh0 = ((uint32_t)__half_as_ushort(h1) << 16) | __half_as_ushort(h0);
            uint32_t hh1 = ((uint32_t)__half_as_ushort(h3) << 16) | __half_as_ushort(h2);
            __half l0 = __float2half_rn(f.x - __half2float(h0));
            __half l1 = __float2half_rn(f.y - __half2float(h1));
            __half l2 = __float2half_rn(f.z - __half2float(h2));
            __half l3 = __float2half_rn(f.w - __half2float(h3));
            uint32_t ll0 = ((uint32_t)__half_as_ushort(l1) << 16) | __half_as_ushort(l0);
            uint32_t ll1 = ((uint32_t)__half_as_ushort(l3) << 16) | __half_as_ushort(l2);
            int off = r * ASTR_A + c4 * 2;
            *(uint2*)(ah + off) = make_uint2(hh0, hh1);
            *(uint2*)(al + off) = make_uint2(ll0, ll1);
        }
    }

    // ldmatrix lane offsets (bytes)
    const int a_off = (warp_m * 32 + (lane & 15)) * ASTR_A + ((lane >> 4) << 4);
    const int b_off = (warp_n * 32 + (lane & 7) + ((lane >> 4) << 3)) * ASTR_B
                    + (((lane >> 3) & 1) << 4);
    const uint32_t ah_base = sb + OFF_AH + a_off;
    const uint32_t al_base = sb + OFF_AL + a_off;

    float sacc[4] = {0.f, 0.f, 0.f, 0.f};   // [mi*2 + half]

    for (int nc = 0; nc < 4; nc++) {
        float acc[2][4][4];
        uint32_t corr[2][4][2];
#pragma unroll
        for (int mi = 0; mi < 2; mi++)
#pragma unroll
            for (int ni = 0; ni < 4; ni++) {
#pragma unroll
                for (int c = 0; c < 4; c++) acc[mi][ni][c] = 0.f;
                corr[mi][ni][0] = 0u; corr[mi][ni][1] = 0u;
            }

        for (int kt = 0; kt < 8; kt++) {
            const int it = nc * 8 + kt;
            const int buf = it & 1;

            CP_WAIT0();
            __syncthreads();        // B tile ready; all warps done with buf^1

            if (it < 31) {
                int nit = it + 1;
                issue_b(wh, wl, sb + OFF_B + (buf ^ 1) * BUF_SZ,
                        nit >> 3, nit & 7, tid);
            }

            const uint32_t bh_b = sb + OFF_B + buf * BUF_SZ + b_off;
            const uint32_t bl_b = bh_b + B_TILE_SZ;
            const int kbase = kt * 128;      // 64 fp16 = 128 bytes

#pragma unroll
            for (int k16 = 0; k16 < 4; k16++) {
                const int ko = kbase + k16 * 32;

                // A fragments for this k16 (m32: two 16-row groups, hi+lo).
                uint32_t ah0[4], ah1[4], al0[4], al1[4];
                ldsm4(ah0, ah_base + ko);
                ldsm4(ah1, ah_base + 16 * ASTR_A + ko);
                ldsm4(al0, al_base + ko);
                ldsm4(al1, al_base + 16 * ASTR_A + ko);

#pragma unroll
                for (int np = 0; np < 2; np++) {
                    const int bo = np * 16 * ASTR_B + k16 * 32;
                    uint32_t bh[4], bl[4];
                    ldsm4(bh, bh_b + bo);
                    ldsm4(bl, bl_b + bo);
                    // main terms: fp32 accumulate
                    mma_f32(acc[0][2 * np],     ah0, bh[0], bh[1]);
                    mma_f32(acc[0][2 * np + 1], ah0, bh[2], bh[3]);
                    mma_f32(acc[1][2 * np],     ah1, bh[0], bh[1]);
                    mma_f32(acc[1][2 * np + 1], ah1, bh[2], bh[3]);
                    // corrections: fp16 accumulate; RAW pairs on the same
                    // accumulator separated by independent MMAs.
                    mma_f16(corr[0][2 * np],     ah0, bl[0], bl[1]);
                    mma_f16(corr[0][2 * np + 1], ah0, bl[2], bl[3]);
                    mma_f16(corr[1][2 * np],     ah1, bl[0], bl[1]);
                    mma_f16(corr[1][2 * np + 1], ah1, bl[2], bl[3]);
                    mma_f16(corr[0][2 * np],     al0, bh[0], bh[1]);
                    mma_f16(corr[0][2 * np + 1], al0, bh[2], bh[3]);
                    mma_f16(corr[1][2 * np],     al1, bh[0], bh[1]);
                    mma_f16(corr[1][2 * np + 1], al1, bh[2], bh[3]);
                }
            }
        }

        // fused partial epilogue for this 128-col chunk
#pragma unroll
        for (int mi = 0; mi < 2; mi++)
#pragma unroll
            for (int ni = 0; ni < 4; ni++) {
                float2 c01 = __half22float2(*(const __half2*)&corr[mi][ni][0]);
                float2 c23 = __half22float2(*(const __half2*)&corr[mi][ni][1]);
                float cf[4] = {c01.x, c01.y, c23.x, c23.y};
#pragma unroll
                for (int c = 0; c < 4; c++) {
                    int n = nc * 128 + warp_n * 32 + ni * 8 + (lane & 3) * 2 + (c & 1);
                    float t = fast_tanh(acc[mi][ni][c] + cf[c] + sbi[n]);
                    sacc[mi * 2 + (c >> 1)] = fmaf(sv[n], t, sacc[mi * 2 + (c >> 1)]);
                }
            }
    }

    // cross-warp reduction: red[64][16]
    __syncthreads();
#pragma unroll
    for (int mi = 0; mi < 2; mi++)
#pragma unroll
        for (int half = 0; half < 2; half++) {
            int m = warp_m * 32 + mi * 16 + half * 8 + (lane >> 2);
            red[m * 16 + warp_n * 4 + (lane & 3)] = sacc[mi * 2 + half];
        }
    __syncthreads();
    if (tid < 64) {
        float s = 0.f;
#pragma unroll
        for (int j = 0; j < 16; j++) s += red[tid * 16 + j];
        scores[row0 + tid] = s;
    }
}

// ---------------------------------------------------------------------------
// Mask dtype detection: numpy bool may be serialized as int32 or uint8.
// ---------------------------------------------------------------------------
__global__ void detect_mask_kernel(const unsigned* __restrict__ mask_words)
{
    if (threadIdx.x == 0) {
        int ok = 1;
        for (int i = 0; i < 256; i++) {
            if (mask_words[i] > 1u) { ok = 0; break; }
        }
        g_mask_is_i32 = ok;
    }
}

// ---------------------------------------------------------------------------
// Masked softmax over S per batch row.
// ---------------------------------------------------------------------------
__global__ __launch_bounds__(256)
void softmax_kernel(const float* __restrict__ scores,
                    const void* __restrict__ mask,
                    float* __restrict__ attn)
{
    const int b = blockIdx.x;
    const int tid = threadIdx.x;
    __shared__ float sred[256];
    __shared__ int s_is_i32;

    if (tid == 0) s_is_i32 = g_mask_is_i32;
    __syncthreads();
    const int is_i32 = s_is_i32;

    const int* mi = (const int*)mask;
    const unsigned char* mu = (const unsigned char*)mask;

    float vals[8];
    float mx = -INFINITY;
#pragma unroll
    for (int j = 0; j < 8; j++) {
        int idx = b * SS + tid + j * 256;
        float sc = scores[idx];
        bool m = is_i32 ? (mi[idx] != 0) : (mu[idx] != 0);
        sc = m ? sc : NEGV;
        vals[j] = sc;
        mx = fmaxf(mx, sc);
    }
    sred[tid] = mx; __syncthreads();
    for (int off = 128; off > 0; off >>= 1) {
        if (tid < off) sred[tid] = fmaxf(sred[tid], sred[tid + off]);
        __syncthreads();
    }
    mx = sred[0]; __syncthreads();

    float sum = 0.f;
#pragma unroll
    for (int j = 0; j < 8; j++) {
        vals[j] = expf(vals[j] - mx);
        sum += vals[j];
    }
    sred[tid] = sum; __syncthreads();
    for (int off = 128; off > 0; off >>= 1) {
        if (tid < off) sred[tid] += sred[tid + off];
        __syncthreads();
    }
    sum = sred[0];

    float inv = 1.f / sum;
#pragma unroll
    for (int j = 0; j < 8; j++) {
        attn[b * SS + tid + j * 256] = vals[j] * inv;
    }
}

// ---------------------------------------------------------------------------
// weighted_output[b,h] = sum_s attn[b,s] * X[b,s,h]
// Stage 1: S split 8 ways -> partials (grid 64x4x8). Stage 2: reduce.
// ---------------------------------------------------------------------------
__global__ __launch_bounds__(128)
void weighted_part_kernel(const float* __restrict__ X,
                          const float* __restrict__ attn,
                          float* __restrict__ part)
{
    const int b  = blockIdx.x;
    const int h  = blockIdx.y * 128 + threadIdx.x;
    const int sc = blockIdx.z;              // 0..7, 256 s each
    const int s0 = sc * 256;
    const float* xb = X + (size_t)b * SS * HH + (size_t)s0 * HH + h;
    const float* ab = attn + b * SS + s0;

    float a0 = 0.f, a1 = 0.f, a2 = 0.f, a3 = 0.f;
#pragma unroll 4
    for (int s = 0; s < 256; s += 4) {
        a0 = fmaf(__ldg(&ab[s + 0]), __ldg(&xb[(size_t)(s + 0) * HH]), a0);
        a1 = fmaf(__ldg(&ab[s + 1]), __ldg(&xb[(size_t)(s + 1) * HH]), a1);
        a2 = fmaf(__ldg(&ab[s + 2]), __ldg(&xb[(size_t)(s + 2) * HH]), a2);
        a3 = fmaf(__ldg(&ab[s + 3]), __ldg(&xb[(size_t)(s + 3) * HH]), a3);
    }
    part[((size_t)sc * BB + b) * HH + h] = (a0 + a1) + (a2 + a3);
}

__global__ __launch_bounds__(256)
void weighted_reduce_kernel(const float* __restrict__ part,
                            float* __restrict__ out)
{
    int idx = blockIdx.x * 256 + threadIdx.x;   // BB*HH = 32768
    float s = 0.f;
#pragma unroll
    for (int j = 0; j < 8; j++) s += part[j * BB * HH + idx];
    out[idx] = s;
}

// ---------------------------------------------------------------------------
extern "C" void kernel_launch(void* const* d_in, const int* in_sizes, int n_in,
                              void* d_out, int out_size)
{
    const float* X    = (const float*)d_in[0];   // [B,S,H]
    const void*  mask = d_in[1];                 // [B,S] bool (int32 or uint8)
    const float* W    = (const float*)d_in[2];   // [H,H]
    const float* bias = (const float*)d_in[3];   // [H]
    const float* v    = (const float*)d_in[4];   // [H]
    float* out = (float*)d_out;

    // Output layout: weighted_output [B,H] first, attn_weights [B,S] second.
    float* attn;
    if (out_size >= BB * HH + TOK) {
        attn = out + BB * HH;
    } else {
        void* p = nullptr;
        cudaGetSymbolAddress(&p, g_attn_fallback);
        attn = (float*)p;
    }
    void* sp = nullptr; cudaGetSymbolAddress(&sp, g_scores);
    float* scores = (float*)sp;
    void* pp = nullptr; cudaGetSymbolAddress(&pp, g_part);
    float* part = (float*)pp;
    void* whp = nullptr; cudaGetSymbolAddress(&whp, g_wh);
    void* wlp = nullptr; cudaGetSymbolAddress(&wlp, g_wl);
    __half* wh = (__half*)whp;
    __half* wl = (__half*)wlp;

    cudaFuncSetAttribute(scores_tc_kernel,
                         cudaFuncAttributeMaxDynamicSharedMemorySize, SMEM_TOTAL);

    detect_mask_kernel<<<1, 32>>>((const unsigned*)mask);   // idx 0
    wsplit_kernel<<<HH * HH / 1024, 256>>>(W, wh, wl);      // idx 1
    dummy_kernel<<<1, 32>>>();                              // idx 2 (ncu slot shim)
    scores_tc_kernel<<<TOK / 64, NTHR, SMEM_TOTAL>>>(X, wh, wl, bias, v, scores); // idx 3
    softmax_kernel<<<BB, 256>>>(scores, mask, attn);
    weighted_part_kernel<<<dim3(BB, HH / 128, 8), 128>>>(X, attn, part);
    weighted_reduce_kernel<<<BB * HH / 256, 256>>>(part, out);
}

// round 10
// speedup vs baseline: 1.0654x; 1.0654x over previous
#include <cuda_runtime.h>
#include <cuda_fp16.h>
#include <cstdint>
#include <math.h>

// Problem dims (fixed by the reference)
#define BB 64
#define SS 2048
#define HH 512
#define TOK (BB * SS)   // 131072
#define NEGV -1e9f

// Scratch (allocations are banned; use device globals)
__device__ float g_scores[TOK];
__device__ float g_attn_fallback[TOK];
__device__ float g_part[8 * BB * HH];
__device__ int   g_mask_is_i32;
__device__ __half g_wh[HH * HH];
__device__ __half g_wl[HH * HH];

// ===========================================================================
// Helpers
// ===========================================================================
__device__ __forceinline__ uint32_t smem_u32(const void* p) {
    uint32_t a;
    asm("{ .reg .u64 t; cvta.to.shared.u64 t, %1; cvt.u32.u64 %0, t; }"
        : "=r"(a) : "l"(p));
    return a;
}
__device__ __forceinline__ void ldsm4(uint32_t (&r)[4], uint32_t addr) {
    asm volatile("ldmatrix.sync.aligned.m8n8.x4.shared.b16 {%0,%1,%2,%3}, [%4];"
        : "=r"(r[0]), "=r"(r[1]), "=r"(r[2]), "=r"(r[3]) : "r"(addr));
}
// fp16 in, fp32 accum
__device__ __forceinline__ void mma_f32(float (&c)[4], const uint32_t (&a)[4],
                                        uint32_t b0, uint32_t b1) {
    asm volatile("mma.sync.aligned.m16n8k16.row.col.f32.f16.f16.f32 "
        "{%0,%1,%2,%3}, {%4,%5,%6,%7}, {%8,%9}, {%0,%1,%2,%3};"
        : "+f"(c[0]), "+f"(c[1]), "+f"(c[2]), "+f"(c[3])
        : "r"(a[0]), "r"(a[1]), "r"(a[2]), "r"(a[3]), "r"(b0), "r"(b1));
}
// fp16 in, fp16 accum
__device__ __forceinline__ void mma_f16(uint32_t (&c)[2], const uint32_t (&a)[4],
                                        uint32_t b0, uint32_t b1) {
    asm volatile("mma.sync.aligned.m16n8k16.row.col.f16.f16.f16.f16 "
        "{%0,%1}, {%2,%3,%4,%5}, {%6,%7}, {%0,%1};"
        : "+r"(c[0]), "+r"(c[1])
        : "r"(a[0]), "r"(a[1]), "r"(a[2]), "r"(a[3]), "r"(b0), "r"(b1));
}
__device__ __forceinline__ void cp16(uint32_t dst, const void* src) {
    asm volatile("cp.async.cg.shared.global [%0], [%1], 16;"
        :: "r"(dst), "l"(src));
}
#define CP_COMMIT() asm volatile("cp.async.commit_group;" ::: "memory")
#define CP_WAIT0()  asm volatile("cp.async.wait_group 0;" ::: "memory")

__device__ __forceinline__ float fast_tanh(float x) {
    x = fminf(15.f, fmaxf(-15.f, x));
    float e = __expf(2.f * x);
    return __fdividef(e - 1.f, e + 1.f);
}

// ===========================================================================
// W pre-split: W fp32 -> Wh, Wl fp16 (global, done once per launch)
// ===========================================================================
__global__ __launch_bounds__(256)
void wsplit_kernel(const float* __restrict__ W,
                   __half* __restrict__ wh,
                   __half* __restrict__ wl)
{
    int idx = blockIdx.x * 256 + threadIdx.x;
#pragma unroll
    for (int j = 0; j < 4; j++) {
        int i = idx * 4 + j;
        float x = W[i];
        __half h = __float2half_rn(x);
        wh[i] = h;
        wl[i] = __float2half_rn(x - __half2float(h));
    }
}

// Tiny no-op so scores_tc lands at ncu's captured launch index (3).
__global__ void dummy_kernel() {}

// ===========================================================================
// Scores kernel: 3-term fp16 split GEMM + fused v.tanh(.+b) epilogue.
// 512 thr / 16 warps, m32n32 warp tiles, SPLIT-K16 warp groups:
//   kg0 (warps 0-7)  processes k16 0..1 of each kt
//   kg1 (warps 8-15) processes k16 2..3 of each kt
// Same (m,n) patches per wid&7; kg1's partial accumulators merged into kg0
// pre-tanh via the just-freed B buffer at each nc boundary.
// Shared traffic 171 B/MMA (m32 B reuse) AND 4 warps/SMSP latency hiding.
// ===========================================================================
#define ASTR_A 1040             // 512 fp16 + 8 pad, bytes
#define ASTR_B 144              // 64 fp16 + 8 pad, bytes
#define A_TILE_SZ (64 * ASTR_A) // 66560
#define B_TILE_SZ (128 * ASTR_B)// 18432
#define OFF_V    0
#define OFF_BI   2048
#define OFF_RED  4096           // 64 x 16 floats
#define OFF_AH   8192
#define OFF_AL   (OFF_AH + A_TILE_SZ)      // 74752
#define OFF_B    (OFF_AL + A_TILE_SZ)      // 141312
#define BUF_SZ   (2 * B_TILE_SZ)           // hi + lo
#define SMEM_TOTAL (OFF_B + 2 * BUF_SZ)    // 215040
// Exchange region: B buffer 1 (free after the last kt of each nc computes
// from it and the next prefetch targets buffer 0). 32KB needed, 36.8KB there.
#define OFF_EX   (OFF_B + BUF_SZ)

#define NTHR 512

__device__ __forceinline__ void issue_b(const __half* __restrict__ wh,
                                        const __half* __restrict__ wl,
                                        uint32_t dst_hi, int nc, int kt, int tid)
{
#pragma unroll
    for (int j = 0; j < 2; j++) {
        int idx = tid + j * NTHR;         // 0..1023
        int row = idx >> 3;               // n row 0..127
        int c16 = idx & 7;                // 16B chunk in k
        uint32_t d = dst_hi + row * ASTR_B + c16 * 16;
        size_t g = (size_t)(nc * 128 + row) * HH + kt * 64 + c16 * 8;
        cp16(d, wh + g);
        cp16(d + B_TILE_SZ, wl + g);
    }
    CP_COMMIT();
}

__global__ __launch_bounds__(NTHR, 1)
void scores_tc_kernel(const float* __restrict__ X,
                      const __half* __restrict__ wh,
                      const __half* __restrict__ wl,
                      const float* __restrict__ bias,
                      const float* __restrict__ v,
                      float* __restrict__ scores)
{
    extern __shared__ char smem[];
    const int tid  = threadIdx.x;
    const int lane = tid & 31;
    const int wid  = tid >> 5;
    const int wid2 = wid & 7;          // patch id (shared between kgs)
    const int kg   = wid >> 3;         // 0: k16 0-1, 1: k16 2-3
    const int warp_m = wid2 & 1;       // 0..1 -> 32-row slab
    const int warp_n = wid2 >> 1;      // 0..3 -> 32-col slab
    const int row0 = blockIdx.x * 64;

    const uint32_t sb = smem_u32(smem);
    float* sv  = (float*)(smem + OFF_V);
    float* sbi = (float*)(smem + OFF_BI);
    float* red = (float*)(smem + OFF_RED);
    float* ex  = (float*)(smem + OFF_EX);
    for (int i = tid; i < HH; i += NTHR) { sv[i] = v[i]; sbi[i] = bias[i]; }

    // Prefetch first B tile.
    issue_b(wh, wl, sb + OFF_B, 0, 0, tid);

    // Convert A (64 x 512) fp32 -> fp16 hi/lo resident tiles, once.
    {
        char* ah = smem + OFF_AH;
        char* al = smem + OFF_AL;
#pragma unroll
        for (int j = 0; j < 16; j++) {
            int idx = tid + j * NTHR;         // 0..8191 float4s
            int r  = idx >> 7;                // row 0..63
            int c4 = (idx & 127) * 4;         // col
            float4 f = *(const float4*)(X + (size_t)(row0 + r) * HH + c4);
            __half h0 = __float2half_rn(f.x);
            __half h1 = __float2half_rn(f.y);
            __half h2 = __float2half_rn(f.z);
            __half h3 = __float2half_rn(f.w);
            uint32_t hh0 = ((uint32_t)__half_as_ushort(h1) << 16) | __half_as_ushort(h0);
            uint32_t hh1 = ((uint32_t)__half_as_ushort(h3) << 16) | __half_as_ushort(h2);
            __half l0 = __float2half_rn(f.x - __half2float(h0));
            __half l1 = __float2half_rn(f.y - __half2float(h1));
            __half l2 = __float2half_rn(f.z - __half2float(h2));
            __half l3 = __float2half_rn(f.w - __half2float(h3));
            uint32_t ll0 = ((uint32_t)__half_as_ushort(l1) << 16) | __half_as_ushort(l0);
            uint32_t ll1 = ((uint32_t)__half_as_ushort(l3) << 16) | __half_as_ushort(l2);
            int off = r * ASTR_A + c4 * 2;
            *(uint2*)(ah + off) = make_uint2(hh0, hh1);
            *(uint2*)(al + off) = make_uint2(ll0, ll1);
        }
    }

    // ldmatrix lane offsets (bytes)
    const int a_off = (warp_m * 32 + (lane & 15)) * ASTR_A + ((lane >> 4) << 4);
    const int b_off = (warp_n * 32 + (lane & 7) + ((lane >> 4) << 3)) * ASTR_B
                    + (((lane >> 3) & 1) << 4);
    const uint32_t ah_base = sb + OFF_AH + a_off;
    const uint32_t al_base = sb + OFF_AL + a_off;

    float sacc[4] = {0.f, 0.f, 0.f, 0.f};   // [mi*2 + half] (kg0 only)

    for (int nc = 0; nc < 4; nc++) {
        float acc[2][4][4];
        uint32_t corr[2][4][2];
#pragma unroll
        for (int mi = 0; mi < 2; mi++)
#pragma unroll
            for (int ni = 0; ni < 4; ni++) {
#pragma unroll
                for (int c = 0; c < 4; c++) acc[mi][ni][c] = 0.f;
                corr[mi][ni][0] = 0u; corr[mi][ni][1] = 0u;
            }

        for (int kt = 0; kt < 8; kt++) {
            const int it = nc * 8 + kt;
            const int buf = it & 1;

            CP_WAIT0();
            __syncthreads();        // B tile ready; all warps done with buf^1

            if (it < 31) {
                int nit = it + 1;
                issue_b(wh, wl, sb + OFF_B + (buf ^ 1) * BUF_SZ,
                        nit >> 3, nit & 7, tid);
            }

            const uint32_t bh_b = sb + OFF_B + buf * BUF_SZ + b_off;
            const uint32_t bl_b = bh_b + B_TILE_SZ;
            const int kbase = kt * 128;      // 64 fp16 = 128 bytes

#pragma unroll
            for (int j = 0; j < 2; j++) {
                const int k16 = kg * 2 + j;          // this kg's k16 slice
                const int ko = kbase + k16 * 32;

                uint32_t ah0[4], ah1[4], al0[4], al1[4];
                ldsm4(ah0, ah_base + ko);
                ldsm4(ah1, ah_base + 16 * ASTR_A + ko);
                ldsm4(al0, al_base + ko);
                ldsm4(al1, al_base + 16 * ASTR_A + ko);

#pragma unroll
                for (int np = 0; np < 2; np++) {
                    const int bo = np * 16 * ASTR_B + k16 * 32;
                    uint32_t bh[4], bl[4];
                    ldsm4(bh, bh_b + bo);
                    ldsm4(bl, bl_b + bo);
                    mma_f32(acc[0][2 * np],     ah0, bh[0], bh[1]);
                    mma_f32(acc[0][2 * np + 1], ah0, bh[2], bh[3]);
                    mma_f32(acc[1][2 * np],     ah1, bh[0], bh[1]);
                    mma_f32(acc[1][2 * np + 1], ah1, bh[2], bh[3]);
                    mma_f16(corr[0][2 * np],     ah0, bl[0], bl[1]);
                    mma_f16(corr[0][2 * np + 1], ah0, bl[2], bl[3]);
                    mma_f16(corr[1][2 * np],     ah1, bl[0], bl[1]);
                    mma_f16(corr[1][2 * np + 1], ah1, bl[2], bl[3]);
                    mma_f16(corr[0][2 * np],     al0, bh[0], bh[1]);
                    mma_f16(corr[0][2 * np + 1], al0, bh[2], bh[3]);
                    mma_f16(corr[1][2 * np],     al1, bh[0], bh[1]);
                    mma_f16(corr[1][2 * np + 1], al1, bh[2], bh[3]);
                }
            }
        }

        // --- merge kg1 partials into kg0, then fused epilogue (kg0 only) ---
        // Fold corr (fp16) into fp32 totals first.
        float accf[2][4][4];
#pragma unroll
        for (int mi = 0; mi < 2; mi++)
#pragma unroll
            for (int ni = 0; ni < 4; ni++) {
                float2 c01 = __half22float2(*(const __half2*)&corr[mi][ni][0]);
                float2 c23 = __half22float2(*(const __half2*)&corr[mi][ni][1]);
                accf[mi][ni][0] = acc[mi][ni][0] + c01.x;
                accf[mi][ni][1] = acc[mi][ni][1] + c01.y;
                accf[mi][ni][2] = acc[mi][ni][2] + c23.x;
                accf[mi][ni][3] = acc[mi][ni][3] + c23.y;
            }

        __syncthreads();   // all MMAs done; B buffer 1 free for exchange
        if (kg == 1) {
#pragma unroll
            for (int mi = 0; mi < 2; mi++)
#pragma unroll
                for (int ni = 0; ni < 4; ni++)
#pragma unroll
                    for (int c = 0; c < 4; c++) {
                        int idx = mi * 16 + ni * 4 + c;
                        ex[idx * 256 + wid2 * 32 + lane] = accf[mi][ni][c];
                    }
        }
        __syncthreads();
        if (kg == 0) {
#pragma unroll
            for (int mi = 0; mi < 2; mi++)
#pragma unroll
                for (int ni = 0; ni < 4; ni++) {
#pragma unroll
                    for (int c = 0; c < 4; c++) {
                        int idx = mi * 16 + ni * 4 + c;
                        accf[mi][ni][c] += ex[idx * 256 + wid2 * 32 + lane];
                    }
#pragma unroll
                    for (int c = 0; c < 4; c++) {
                        int n = nc * 128 + warp_n * 32 + ni * 8 + (lane & 3) * 2 + (c & 1);
                        float t = fast_tanh(accf[mi][ni][c] + sbi[n]);
                        sacc[mi * 2 + (c >> 1)] = fmaf(sv[n], t, sacc[mi * 2 + (c >> 1)]);
                    }
                }
        }
        __syncthreads();   // exchange reads done before next nc's prefetch writes
    }

    // cross-warp reduction (kg0 warps only): red[64][16]
    if (kg == 0) {
#pragma unroll
        for (int mi = 0; mi < 2; mi++)
#pragma unroll
            for (int half = 0; half < 2; half++) {
                int m = warp_m * 32 + mi * 16 + half * 8 + (lane >> 2);
                red[m * 16 + warp_n * 4 + (lane & 3)] = sacc[mi * 2 + half];
            }
    }
    __syncthreads();
    if (tid < 64) {
        float s = 0.f;
#pragma unroll
        for (int j = 0; j < 16; j++) s += red[tid * 16 + j];
        scores[row0 + tid] = s;
    }
}

// ---------------------------------------------------------------------------
// Mask dtype detection: numpy bool may be serialized as int32 or uint8.
// ---------------------------------------------------------------------------
__global__ void detect_mask_kernel(const unsigned* __restrict__ mask_words)
{
    if (threadIdx.x == 0) {
        int ok = 1;
        for (int i = 0; i < 256; i++) {
            if (mask_words[i] > 1u) { ok = 0; break; }
        }
        g_mask_is_i32 = ok;
    }
}

// ---------------------------------------------------------------------------
// Masked softmax over S per batch row.
// ---------------------------------------------------------------------------
__global__ __launch_bounds__(256)
void softmax_kernel(const float* __restrict__ scores,
                    const void* __restrict__ mask,
                    float* __restrict__ attn)
{
    const int b = blockIdx.x;
    const int tid = threadIdx.x;
    __shared__ float sred[256];
    __shared__ int s_is_i32;

    if (tid == 0) s_is_i32 = g_mask_is_i32;
    __syncthreads();
    const int is_i32 = s_is_i32;

    const int* mi = (const int*)mask;
    const unsigned char* mu = (const unsigned char*)mask;

    float vals[8];
    float mx = -INFINITY;
#pragma unroll
    for (int j = 0; j < 8; j++) {
        int idx = b * SS + tid + j * 256;
        float sc = scores[idx];
        bool m = is_i32 ? (mi[idx] != 0) : (mu[idx] != 0);
        sc = m ? sc : NEGV;
        vals[j] = sc;
        mx = fmaxf(mx, sc);
    }
    sred[tid] = mx; __syncthreads();
    for (int off = 128; off > 0; off >>= 1) {
        if (tid < off) sred[tid] = fmaxf(sred[tid], sred[tid + off]);
        __syncthreads();
    }
    mx = sred[0]; __syncthreads();

    float sum = 0.f;
#pragma unroll
    for (int j = 0; j < 8; j++) {
        vals[j] = expf(vals[j] - mx);
        sum += vals[j];
    }
    sred[tid] = sum; __syncthreads();
    for (int off = 128; off > 0; off >>= 1) {
        if (tid < off) sred[tid] += sred[tid + off];
        __syncthreads();
    }
    sum = sred[0];

    float inv = 1.f / sum;
#pragma unroll
    for (int j = 0; j < 8; j++) {
        attn[b * SS + tid + j * 256] = vals[j] * inv;
    }
}

// ---------------------------------------------------------------------------
// weighted_output[b,h] = sum_s attn[b,s] * X[b,s,h]
// Stage 1: S split 8 ways -> partials (grid 64x4x8). Stage 2: reduce.
// ---------------------------------------------------------------------------
__global__ __launch_bounds__(128)
void weighted_part_kernel(const float* __restrict__ X,
                          const float* __restrict__ attn,
                          float* __restrict__ part)
{
    const int b  = blockIdx.x;
    const int h  = blockIdx.y * 128 + threadIdx.x;
    const int sc = blockIdx.z;              // 0..7, 256 s each
    const int s0 = sc * 256;
    const float* xb = X + (size_t)b * SS * HH + (size_t)s0 * HH + h;
    const float* ab = attn + b * SS + s0;

    float a0 = 0.f, a1 = 0.f, a2 = 0.f, a3 = 0.f;
#pragma unroll 4
    for (int s = 0; s < 256; s += 4) {
        a0 = fmaf(__ldg(&ab[s + 0]), __ldg(&xb[(size_t)(s + 0) * HH]), a0);
        a1 = fmaf(__ldg(&ab[s + 1]), __ldg(&xb[(size_t)(s + 1) * HH]), a1);
        a2 = fmaf(__ldg(&ab[s + 2]), __ldg(&xb[(size_t)(s + 2) * HH]), a2);
        a3 = fmaf(__ldg(&ab[s + 3]), __ldg(&xb[(size_t)(s + 3) * HH]), a3);
    }
    part[((size_t)sc * BB + b) * HH + h] = (a0 + a1) + (a2 + a3);
}

__global__ __launch_bounds__(256)
void weighted_reduce_kernel(const float* __restrict__ part,
                            float* __restrict__ out)
{
    int idx = blockIdx.x * 256 + threadIdx.x;   // BB*HH = 32768
    float s = 0.f;
#pragma unroll
    for (int j = 0; j < 8; j++) s += part[j * BB * HH + idx];
    out[idx] = s;
}

// ---------------------------------------------------------------------------
extern "C" void kernel_launch(void* const* d_in, const int* in_sizes, int n_in,
                              void* d_out, int out_size)
{
    const float* X    = (const float*)d_in[0];   // [B,S,H]
    const void*  mask = d_in[1];                 // [B,S] bool (int32 or uint8)
    const float* W    = (const float*)d_in[2];   // [H,H]
    const float* bias = (const float*)d_in[3];   // [H]
    const float* v    = (const float*)d_in[4];   // [H]
    float* out = (float*)d_out;

    // Output layout: weighted_output [B,H] first, attn_weights [B,S] second.
    float* attn;
    if (out_size >= BB * HH + TOK) {
        attn = out + BB * HH;
    } else {
        void* p = nullptr;
        cudaGetSymbolAddress(&p, g_attn_fallback);
        attn = (float*)p;
    }
    void* sp = nullptr; cudaGetSymbolAddress(&sp, g_scores);
    float* scores = (float*)sp;
    void* pp = nullptr; cudaGetSymbolAddress(&pp, g_part);
    float* part = (float*)pp;
    void* whp = nullptr; cudaGetSymbolAddress(&whp, g_wh);
    void* wlp = nullptr; cudaGetSymbolAddress(&wlp, g_wl);
    __half* wh = (__half*)whp;
    __half* wl = (__half*)wlp;

    cudaFuncSetAttribute(scores_tc_kernel,
                         cudaFuncAttributeMaxDynamicSharedMemorySize, SMEM_TOTAL);

    detect_mask_kernel<<<1, 32>>>((const unsigned*)mask);   // idx 0
    wsplit_kernel<<<HH * HH / 1024, 256>>>(W, wh, wl);      // idx 1
    dummy_kernel<<<1, 32>>>();                              // idx 2 (ncu slot shim)
    scores_tc_kernel<<<TOK / 64, NTHR, SMEM_TOTAL>>>(X, wh, wl, bias, v, scores); // idx 3
    softmax_kernel<<<BB, 256>>>(scores, mask, attn);
    weighted_part_kernel<<<dim3(BB, HH / 128, 8), 128>>>(X, attn, part);
    weighted_reduce_kernel<<<BB * HH / 256, 256>>>(part, out);
}

// round 11
// speedup vs baseline: 1.0972x; 1.0299x over previous
#include <cuda_runtime.h>
#include <cuda_fp16.h>
#include <cstdint>
#include <math.h>

// Problem dims (fixed by the reference)
#define BB 64
#define SS 2048
#define HH 512
#define TOK (BB * SS)   // 131072
#define NEGV -1e9f

// Scratch (allocations are banned; use device globals)
__device__ float g_scores[TOK];
__device__ float g_attn_fallback[TOK];
__device__ float g_part[8 * BB * HH];
__device__ int   g_mask_is_i32;
__device__ __half g_wh[HH * HH];
__device__ __half g_wl[HH * HH];

// ===========================================================================
// Helpers
// ===========================================================================
__device__ __forceinline__ uint32_t smem_u32(const void* p) {
    uint32_t a;
    asm("{ .reg .u64 t; cvta.to.shared.u64 t, %1; cvt.u32.u64 %0, t; }"
        : "=r"(a) : "l"(p));
    return a;
}
__device__ __forceinline__ void ldsm4(uint32_t (&r)[4], uint32_t addr) {
    asm volatile("ldmatrix.sync.aligned.m8n8.x4.shared.b16 {%0,%1,%2,%3}, [%4];"
        : "=r"(r[0]), "=r"(r[1]), "=r"(r[2]), "=r"(r[3]) : "r"(addr));
}
// fp16 in, fp32 accum
__device__ __forceinline__ void mma_f32(float (&c)[4], const uint32_t (&a)[4],
                                        uint32_t b0, uint32_t b1) {
    asm volatile("mma.sync.aligned.m16n8k16.row.col.f32.f16.f16.f32 "
        "{%0,%1,%2,%3}, {%4,%5,%6,%7}, {%8,%9}, {%0,%1,%2,%3};"
        : "+f"(c[0]), "+f"(c[1]), "+f"(c[2]), "+f"(c[3])
        : "r"(a[0]), "r"(a[1]), "r"(a[2]), "r"(a[3]), "r"(b0), "r"(b1));
}
// fp16 in, fp16 accum
__device__ __forceinline__ void mma_f16(uint32_t (&c)[2], const uint32_t (&a)[4],
                                        uint32_t b0, uint32_t b1) {
    asm volatile("mma.sync.aligned.m16n8k16.row.col.f16.f16.f16.f16 "
        "{%0,%1}, {%2,%3,%4,%5}, {%6,%7}, {%0,%1};"
        : "+r"(c[0]), "+r"(c[1])
        : "r"(a[0]), "r"(a[1]), "r"(a[2]), "r"(a[3]), "r"(b0), "r"(b1));
}
__device__ __forceinline__ void cp16(uint32_t dst, const void* src) {
    asm volatile("cp.async.cg.shared.global [%0], [%1], 16;"
        :: "r"(dst), "l"(src));
}
#define CP_COMMIT() asm volatile("cp.async.commit_group;" ::: "memory")
#define CP_WAIT0()  asm volatile("cp.async.wait_group 0;" ::: "memory")

__device__ __forceinline__ float fast_tanh(float x) {
    x = fminf(15.f, fmaxf(-15.f, x));
    float e = __expf(2.f * x);
    return __fdividef(e - 1.f, e + 1.f);
}

// ===========================================================================
// W pre-split: W fp32 -> Wh, Wl fp16 (global, done once per launch)
// ===========================================================================
__global__ __launch_bounds__(256)
void wsplit_kernel(const float* __restrict__ W,
                   __half* __restrict__ wh,
                   __half* __restrict__ wl)
{
    int idx = blockIdx.x * 256 + threadIdx.x;
#pragma unroll
    for (int j = 0; j < 4; j++) {
        int i = idx * 4 + j;
        float x = W[i];
        __half h = __float2half_rn(x);
        wh[i] = h;
        wl[i] = __float2half_rn(x - __half2float(h));
    }
}

// Tiny no-op so scores_tc lands at ncu's captured launch index (3).
__global__ void dummy_kernel() {}

// ===========================================================================
// Scores kernel: 3-term fp16 split GEMM + fused v.tanh(.+b) epilogue.
// 256 thr / 8 warps, m32n32 warp tiles. SMEM cut to 112 KB so TWO CTAs
// co-reside per SM: each CTA's MMAs cover the other's barrier/drain.
// A is STREAMED per kt (LDG fp32 prefetch -> cvt -> 2-stage hi/lo smem ring);
// X re-read per nc hits L2 (wave working set 38MB < 126MB L2).
// B (Wh/Wl) streamed via cp.async double buffer as before. BK=64.
// ===========================================================================
#define ASTR_A 144              // 64 fp16 + 8 pad, bytes (16B-aligned rows)
#define ASTR_B 144
#define A_TILE_SZ (64 * ASTR_A)  // 9216 per (stage,hi/lo)
#define B_TILE_SZ (128 * ASTR_B) // 18432 per (stage,hi/lo)
#define B_BUF_SZ  (2 * B_TILE_SZ)// 36864 per stage (hi+lo)
#define OFF_V    0
#define OFF_BI   2048
#define OFF_A    4096                       // AH0,AL0,AH1,AL1 -> 4*9216
#define OFF_B    (OFF_A + 4 * A_TILE_SZ)    // 40960; BH0,BL0,BH1,BL1
#define SMEM_TOTAL (OFF_B + 2 * B_BUF_SZ)   // 114688 (112 KB) -> 2 CTAs/SM
#define OFF_RED  OFF_B                      // reuse dead B ring for reduction

#define NTHR 256

__device__ __forceinline__ void issue_b(const __half* __restrict__ wh,
                                        const __half* __restrict__ wl,
                                        uint32_t dst_hi, int nc, int kt, int tid)
{
#pragma unroll
    for (int j = 0; j < 4; j++) {
        int idx = tid + j * NTHR;         // 0..1023
        int row = idx >> 3;               // n row 0..127
        int c16 = idx & 7;                // 16B chunk in k
        uint32_t d = dst_hi + row * ASTR_B + c16 * 16;
        size_t g = (size_t)(nc * 128 + row) * HH + kt * 64 + c16 * 8;
        cp16(d, wh + g);
        cp16(d + B_TILE_SZ, wl + g);
    }
    CP_COMMIT();
}

// Convert 4 float4 (one 64x64 A chunk slice per thread) and store hi/lo.
__device__ __forceinline__ void store_a(const float4 (&ar)[4],
                                        char* ah, char* al, int tid)
{
#pragma unroll
    for (int j = 0; j < 4; j++) {
        int idx = tid + j * NTHR;         // 0..1023
        int r  = idx >> 4;                // row 0..63
        int c4 = (idx & 15) * 4;          // col (fp32 units)
        float4 f = ar[j];
        __half h0 = __float2half_rn(f.x);
        __half h1 = __float2half_rn(f.y);
        __half h2 = __float2half_rn(f.z);
        __half h3 = __float2half_rn(f.w);
        uint32_t hh0 = ((uint32_t)__half_as_ushort(h1) << 16) | __half_as_ushort(h0);
        uint32_t hh1 = ((uint32_t)__half_as_ushort(h3) << 16) | __half_as_ushort(h2);
        __half l0 = __float2half_rn(f.x - __half2float(h0));
        __half l1 = __float2half_rn(f.y - __half2float(h1));
        __half l2 = __float2half_rn(f.z - __half2float(h2));
        __half l3 = __float2half_rn(f.w - __half2float(h3));
        uint32_t ll0 = ((uint32_t)__half_as_ushort(l1) << 16) | __half_as_ushort(l0);
        uint32_t ll1 = ((uint32_t)__half_as_ushort(l3) << 16) | __half_as_ushort(l2);
        int off = r * ASTR_A + c4 * 2;
        *(uint2*)(ah + off) = make_uint2(hh0, hh1);
        *(uint2*)(al + off) = make_uint2(ll0, ll1);
    }
}

__global__ __launch_bounds__(NTHR, 2)
void scores_tc_kernel(const float* __restrict__ X,
                      const __half* __restrict__ wh,
                      const __half* __restrict__ wl,
                      const float* __restrict__ bias,
                      const float* __restrict__ v,
                      float* __restrict__ scores)
{
    extern __shared__ char smem[];
    const int tid  = threadIdx.x;
    const int lane = tid & 31;
    const int wid  = tid >> 5;
    const int warp_m = wid & 1;        // 0..1 -> 32-row slab
    const int warp_n = wid >> 1;       // 0..3 -> 32-col slab
    const int row0 = blockIdx.x * 64;

    const uint32_t sb = smem_u32(smem);
    float* sv  = (float*)(smem + OFF_V);
    float* sbi = (float*)(smem + OFF_BI);
    for (int i = tid; i < HH; i += NTHR) { sv[i] = v[i]; sbi[i] = bias[i]; }

    // Prefetch first B tile (it = 0 -> buf 0).
    issue_b(wh, wl, sb + OFF_B, 0, 0, tid);

    // Prologue: A chunk k=0 -> stage 0 (visible at kt=0's syncthreads).
    {
        float4 ar[4];
#pragma unroll
        for (int j = 0; j < 4; j++) {
            int idx = tid + j * NTHR;
            int r  = idx >> 4;
            int c4 = (idx & 15) * 4;
            ar[j] = *(const float4*)(X + (size_t)(row0 + r) * HH + c4);
        }
        store_a(ar, smem + OFF_A, smem + OFF_A + A_TILE_SZ, tid);
    }

    // ldmatrix lane offsets (bytes)
    const int a_off = (warp_m * 32 + (lane & 15)) * ASTR_A + ((lane >> 4) << 4);
    const int b_off = (warp_n * 32 + (lane & 7) + ((lane >> 4) << 3)) * ASTR_B
                    + (((lane >> 3) & 1) << 4);

    float sacc[4] = {0.f, 0.f, 0.f, 0.f};   // [mi*2 + half]

    for (int nc = 0; nc < 4; nc++) {
        float acc[2][4][4];
        uint32_t corr[2][4][2];
#pragma unroll
        for (int mi = 0; mi < 2; mi++)
#pragma unroll
            for (int ni = 0; ni < 4; ni++) {
#pragma unroll
                for (int c = 0; c < 4; c++) acc[mi][ni][c] = 0.f;
                corr[mi][ni][0] = 0u; corr[mi][ni][1] = 0u;
            }

        for (int kt = 0; kt < 8; kt++) {
            const int it = nc * 8 + kt;
            const int buf = it & 1;
            const int stage = kt & 1;
            const bool have_next = (it < 31);

            CP_WAIT0();
            __syncthreads();        // B(kt) + A(kt) stage ready; prev bufs free

            if (have_next) {
                int nit = it + 1;
                issue_b(wh, wl, sb + OFF_B + (buf ^ 1) * B_BUF_SZ,
                        nit >> 3, nit & 7, tid);
            }

            // Prefetch next A chunk (fp32) into registers; LDG latency is
            // hidden by the MMA section below. Chunk k depends on kt only.
            float4 ar[4];
            if (have_next) {
                const int nkt = (kt + 1) & 7;
#pragma unroll
                for (int j = 0; j < 4; j++) {
                    int idx = tid + j * NTHR;
                    int r  = idx >> 4;
                    int c4 = (idx & 15) * 4;
                    ar[j] = *(const float4*)(X + (size_t)(row0 + r) * HH
                                             + nkt * 64 + c4);
                }
            }

            const uint32_t ah_base = sb + OFF_A + stage * 2 * A_TILE_SZ + a_off;
            const uint32_t al_base = ah_base + A_TILE_SZ;
            const uint32_t bh_b = sb + OFF_B + buf * B_BUF_SZ + b_off;
            const uint32_t bl_b = bh_b + B_TILE_SZ;

#pragma unroll
            for (int k16 = 0; k16 < 4; k16++) {
                const int ko = k16 * 32;
                uint32_t ah0[4], ah1[4], al0[4], al1[4];
                ldsm4(ah0, ah_base + ko);
                ldsm4(ah1, ah_base + 16 * ASTR_A + ko);
                ldsm4(al0, al_base + ko);
                ldsm4(al1, al_base + 16 * ASTR_A + ko);
#pragma unroll
                for (int np = 0; np < 2; np++) {
                    const int bo = np * 16 * ASTR_B + ko;
                    uint32_t bh[4], bl[4];
                    ldsm4(bh, bh_b + bo);
                    ldsm4(bl, bl_b + bo);
                    mma_f32(acc[0][2 * np],     ah0, bh[0], bh[1]);
                    mma_f32(acc[0][2 * np + 1], ah0, bh[2], bh[3]);
                    mma_f32(acc[1][2 * np],     ah1, bh[0], bh[1]);
                    mma_f32(acc[1][2 * np + 1], ah1, bh[2], bh[3]);
                    mma_f16(corr[0][2 * np],     ah0, bl[0], bl[1]);
                    mma_f16(corr[0][2 * np + 1], ah0, bl[2], bl[3]);
                    mma_f16(corr[1][2 * np],     ah1, bl[0], bl[1]);
                    mma_f16(corr[1][2 * np + 1], ah1, bl[2], bl[3]);
                    mma_f16(corr[0][2 * np],     al0, bh[0], bh[1]);
                    mma_f16(corr[0][2 * np + 1], al0, bh[2], bh[3]);
                    mma_f16(corr[1][2 * np],     al1, bh[0], bh[1]);
                    mma_f16(corr[1][2 * np + 1], al1, bh[2], bh[3]);
                }
            }

            // Convert + store next A chunk into the other stage. Readers
            // sync at the top of the next kt iteration.
            if (have_next) {
                char* ahd = smem + OFF_A + (stage ^ 1) * 2 * A_TILE_SZ;
                store_a(ar, ahd, ahd + A_TILE_SZ, tid);
            }
        }

        // fused partial epilogue for this 128-col chunk
#pragma unroll
        for (int mi = 0; mi < 2; mi++)
#pragma unroll
            for (int ni = 0; ni < 4; ni++) {
                float2 c01 = __half22float2(*(const __half2*)&corr[mi][ni][0]);
                float2 c23 = __half22float2(*(const __half2*)&corr[mi][ni][1]);
                float cf[4] = {c01.x, c01.y, c23.x, c23.y};
#pragma unroll
                for (int c = 0; c < 4; c++) {
                    int n = nc * 128 + warp_n * 32 + ni * 8 + (lane & 3) * 2 + (c & 1);
                    float t = fast_tanh(acc[mi][ni][c] + cf[c] + sbi[n]);
                    sacc[mi * 2 + (c >> 1)] = fmaf(sv[n], t, sacc[mi * 2 + (c >> 1)]);
                }
            }
    }

    // cross-warp reduction: red[64][16] aliases the (dead) B ring.
    float* red = (float*)(smem + OFF_RED);
    __syncthreads();   // all B reads done before aliasing
#pragma unroll
    for (int mi = 0; mi < 2; mi++)
#pragma unroll
        for (int half = 0; half < 2; half++) {
            int m = warp_m * 32 + mi * 16 + half * 8 + (lane >> 2);
            red[m * 16 + warp_n * 4 + (lane & 3)] = sacc[mi * 2 + half];
        }
    __syncthreads();
    if (tid < 64) {
        float s = 0.f;
#pragma unroll
        for (int j = 0; j < 16; j++) s += red[tid * 16 + j];
        scores[row0 + tid] = s;
    }
}

// ---------------------------------------------------------------------------
// Mask dtype detection: numpy bool may be serialized as int32 or uint8.
// ---------------------------------------------------------------------------
__global__ void detect_mask_kernel(const unsigned* __restrict__ mask_words)
{
    if (threadIdx.x == 0) {
        int ok = 1;
        for (int i = 0; i < 256; i++) {
            if (mask_words[i] > 1u) { ok = 0; break; }
        }
        g_mask_is_i32 = ok;
    }
}

// ---------------------------------------------------------------------------
// Masked softmax over S per batch row.
// ---------------------------------------------------------------------------
__global__ __launch_bounds__(256)
void softmax_kernel(const float* __restrict__ scores,
                    const void* __restrict__ mask,
                    float* __restrict__ attn)
{
    const int b = blockIdx.x;
    const int tid = threadIdx.x;
    __shared__ float sred[256];
    __shared__ int s_is_i32;

    if (tid == 0) s_is_i32 = g_mask_is_i32;
    __syncthreads();
    const int is_i32 = s_is_i32;

    const int* mi = (const int*)mask;
    const unsigned char* mu = (const unsigned char*)mask;

    float vals[8];
    float mx = -INFINITY;
#pragma unroll
    for (int j = 0; j < 8; j++) {
        int idx = b * SS + tid + j * 256;
        float sc = scores[idx];
        bool m = is_i32 ? (mi[idx] != 0) : (mu[idx] != 0);
        sc = m ? sc : NEGV;
        vals[j] = sc;
        mx = fmaxf(mx, sc);
    }
    sred[tid] = mx; __syncthreads();
    for (int off = 128; off > 0; off >>= 1) {
        if (tid < off) sred[tid] = fmaxf(sred[tid], sred[tid + off]);
        __syncthreads();
    }
    mx = sred[0]; __syncthreads();

    float sum = 0.f;
#pragma unroll
    for (int j = 0; j < 8; j++) {
        vals[j] = expf(vals[j] - mx);
        sum += vals[j];
    }
    sred[tid] = sum; __syncthreads();
    for (int off = 128; off > 0; off >>= 1) {
        if (tid < off) sred[tid] += sred[tid + off];
        __syncthreads();
    }
    sum = sred[0];

    float inv = 1.f / sum;
#pragma unroll
    for (int j = 0; j < 8; j++) {
        attn[b * SS + tid + j * 256] = vals[j] * inv;
    }
}

// ---------------------------------------------------------------------------
// weighted_output[b,h] = sum_s attn[b,s] * X[b,s,h]
// Stage 1: S split 8 ways -> partials (grid 64x4x8). Stage 2: reduce.
// ---------------------------------------------------------------------------
__global__ __launch_bounds__(128)
void weighted_part_kernel(const float* __restrict__ X,
                          const float* __restrict__ attn,
                          float* __restrict__ part)
{
    const int b  = blockIdx.x;
    const int h  = blockIdx.y * 128 + threadIdx.x;
    const int sc = blockIdx.z;              // 0..7, 256 s each
    const int s0 = sc * 256;
    const float* xb = X + (size_t)b * SS * HH + (size_t)s0 * HH + h;
    const float* ab = attn + b * SS + s0;

    float a0 = 0.f, a1 = 0.f, a2 = 0.f, a3 = 0.f;
#pragma unroll 4
    for (int s = 0; s < 256; s += 4) {
        a0 = fmaf(__ldg(&ab[s + 0]), __ldg(&xb[(size_t)(s + 0) * HH]), a0);
        a1 = fmaf(__ldg(&ab[s + 1]), __ldg(&xb[(size_t)(s + 1) * HH]), a1);
        a2 = fmaf(__ldg(&ab[s + 2]), __ldg(&xb[(size_t)(s + 2) * HH]), a2);
        a3 = fmaf(__ldg(&ab[s + 3]), __ldg(&xb[(size_t)(s + 3) * HH]), a3);
    }
    part[((size_t)sc * BB + b) * HH + h] = (a0 + a1) + (a2 + a3);
}

__global__ __launch_bounds__(256)
void weighted_reduce_kernel(const float* __restrict__ part,
                            float* __restrict__ out)
{
    int idx = blockIdx.x * 256 + threadIdx.x;   // BB*HH = 32768
    float s = 0.f;
#pragma unroll
    for (int j = 0; j < 8; j++) s += part[j * BB * HH + idx];
    out[idx] = s;
}

// ---------------------------------------------------------------------------
extern "C" void kernel_launch(void* const* d_in, const int* in_sizes, int n_in,
                              void* d_out, int out_size)
{
    const float* X    = (const float*)d_in[0];   // [B,S,H]
    const void*  mask = d_in[1];                 // [B,S] bool (int32 or uint8)
    const float* W    = (const float*)d_in[2];   // [H,H]
    const float* bias = (const float*)d_in[3];   // [H]
    const float* v    = (const float*)d_in[4];   // [H]
    float* out = (float*)d_out;

    // Output layout: weighted_output [B,H] first, attn_weights [B,S] second.
    float* attn;
    if (out_size >= BB * HH + TOK) {
        attn = out + BB * HH;
    } else {
        void* p = nullptr;
        cudaGetSymbolAddress(&p, g_attn_fallback);
        attn = (float*)p;
    }
    void* sp = nullptr; cudaGetSymbolAddress(&sp, g_scores);
    float* scores = (float*)sp;
    void* pp = nullptr; cudaGetSymbolAddress(&pp, g_part);
    float* part = (float*)pp;
    void* whp = nullptr; cudaGetSymbolAddress(&whp, g_wh);
    void* wlp = nullptr; cudaGetSymbolAddress(&wlp, g_wl);
    __half* wh = (__half*)whp;
    __half* wl = (__half*)wlp;

    cudaFuncSetAttribute(scores_tc_kernel,
                         cudaFuncAttributeMaxDynamicSharedMemorySize, SMEM_TOTAL);

    detect_mask_kernel<<<1, 32>>>((const unsigned*)mask);   // idx 0
    wsplit_kernel<<<HH * HH / 1024, 256>>>(W, wh, wl);      // idx 1
    dummy_kernel<<<1, 32>>>();                              // idx 2 (ncu slot shim)
    scores_tc_kernel<<<TOK / 64, NTHR, SMEM_TOTAL>>>(X, wh, wl, bias, v, scores); // idx 3
    softmax_kernel<<<BB, 256>>>(scores, mask, attn);
    weighted_part_kernel<<<dim3(BB, HH / 128, 8), 128>>>(X, attn, part);
    weighted_reduce_kernel<<<BB * HH / 256, 256>>>(part, out);
}

// round 12
// speedup vs baseline: 1.1055x; 1.0076x over previous
#include <cuda_runtime.h>
#include <cuda_fp16.h>
#include <cstdint>
#include <math.h>

// Problem dims (fixed by the reference)
#define BB 64
#define SS 2048
#define HH 512
#define TOK (BB * SS)   // 131072
#define NEGV -1e9f

// Scratch (allocations are banned; use device globals)
__device__ float g_scores[TOK];
__device__ float g_attn_fallback[TOK];
__device__ float g_part[8 * BB * HH];
__device__ int   g_mask_is_i32;
__device__ __half g_wh[HH * HH];
__device__ __half g_wl[HH * HH];

// ===========================================================================
// Helpers
// ===========================================================================
__device__ __forceinline__ uint32_t smem_u32(const void* p) {
    uint32_t a;
    asm("{ .reg .u64 t; cvta.to.shared.u64 t, %1; cvt.u32.u64 %0, t; }"
        : "=r"(a) : "l"(p));
    return a;
}
__device__ __forceinline__ void ldsm4(uint32_t (&r)[4], uint32_t addr) {
    asm volatile("ldmatrix.sync.aligned.m8n8.x4.shared.b16 {%0,%1,%2,%3}, [%4];"
        : "=r"(r[0]), "=r"(r[1]), "=r"(r[2]), "=r"(r[3]) : "r"(addr));
}
// fp16 in, fp32 accum
__device__ __forceinline__ void mma_f32(float (&c)[4], const uint32_t (&a)[4],
                                        uint32_t b0, uint32_t b1) {
    asm volatile("mma.sync.aligned.m16n8k16.row.col.f32.f16.f16.f32 "
        "{%0,%1,%2,%3}, {%4,%5,%6,%7}, {%8,%9}, {%0,%1,%2,%3};"
        : "+f"(c[0]), "+f"(c[1]), "+f"(c[2]), "+f"(c[3])
        : "r"(a[0]), "r"(a[1]), "r"(a[2]), "r"(a[3]), "r"(b0), "r"(b1));
}
// fp16 in, fp16 accum
__device__ __forceinline__ void mma_f16(uint32_t (&c)[2], const uint32_t (&a)[4],
                                        uint32_t b0, uint32_t b1) {
    asm volatile("mma.sync.aligned.m16n8k16.row.col.f16.f16.f16.f16 "
        "{%0,%1}, {%2,%3,%4,%5}, {%6,%7}, {%0,%1};"
        : "+r"(c[0]), "+r"(c[1])
        : "r"(a[0]), "r"(a[1]), "r"(a[2]), "r"(a[3]), "r"(b0), "r"(b1));
}
__device__ __forceinline__ void cp16(uint32_t dst, const void* src) {
    asm volatile("cp.async.cg.shared.global [%0], [%1], 16;"
        :: "r"(dst), "l"(src));
}
#define CP_COMMIT() asm volatile("cp.async.commit_group;" ::: "memory")
#define CP_WAIT0()  asm volatile("cp.async.wait_group 0;" ::: "memory")

__device__ __forceinline__ float fast_tanh(float x) {
    x = fminf(15.f, fmaxf(-15.f, x));
    float e = __expf(2.f * x);
    return __fdividef(e - 1.f, e + 1.f);
}

// ===========================================================================
// W pre-split: W fp32 -> Wh, Wl fp16 (global, done once per launch)
// ===========================================================================
__global__ __launch_bounds__(256)
void wsplit_kernel(const float* __restrict__ W,
                   __half* __restrict__ wh,
                   __half* __restrict__ wl)
{
    int idx = blockIdx.x * 256 + threadIdx.x;
#pragma unroll
    for (int j = 0; j < 4; j++) {
        int i = idx * 4 + j;
        float x = W[i];
        __half h = __float2half_rn(x);
        wh[i] = h;
        wl[i] = __float2half_rn(x - __half2float(h));
    }
}

// Tiny no-op so scores_tc lands at ncu's captured launch index (3).
__global__ void dummy_kernel() {}

// ===========================================================================
// Scores kernel: 3-term fp16 split GEMM + fused v.tanh(.+b) epilogue.
// SMEM-port bound (HMMA is full rate) -> minimize bytes/MMA:
// warp tile m48 x n32: 10 ldsm serve 36 MMAs = 142 B/MMA (vs 171 at m32).
// Block tile M=96 x N=128, BK=32, 256 thr (8 warps: 2 warp_m x 4 warp_n),
// 2 CTAs/SM (smem ~74 KB, regs clamped to 128). Grid 1366; tail block
// clamps loads to row TOK-1 and predicates score stores.
// A streamed per kt (LDG fp32 -> hi/lo ring), B (Wh/Wl) via cp.async ring.
// ===========================================================================
#define ASTR 80                  // 32 fp16 = 64B + 16 pad (16B-mult, ldsm-clean)
#define A_PLANE (96 * ASTR)      // 7680
#define A_STAGE (2 * A_PLANE)    // 15360 (hi+lo)
#define B_PLANE (128 * ASTR)     // 10240
#define B_STAGE (2 * B_PLANE)    // 20480 (hi+lo)
#define OFF_V    0
#define OFF_BI   2048
#define OFF_A    4096
#define OFF_B    (OFF_A + 2 * A_STAGE)      // 34816
#define SMEM_TOTAL (OFF_B + 2 * B_STAGE)    // 75776 -> 2 CTAs/SM
#define OFF_RED  OFF_B                      // reuse dead B ring for reduction

#define NTHR 256
#define BM 96
#define GRID_M ((TOK + BM - 1) / BM)        // 1366

__device__ __forceinline__ void issue_b(const __half* __restrict__ wh,
                                        const __half* __restrict__ wl,
                                        uint32_t dst_hi, int nc, int kt, int tid)
{
#pragma unroll
    for (int j = 0; j < 2; j++) {
        int idx = tid + j * NTHR;         // 0..511
        int row = idx >> 2;               // n row 0..127
        int c16 = idx & 3;                // 16B chunk (4 per 64B row)
        uint32_t d = dst_hi + row * ASTR + c16 * 16;
        size_t g = (size_t)(nc * 128 + row) * HH + kt * 32 + c16 * 8;
        cp16(d, wh + g);
        cp16(d + B_PLANE, wl + g);
    }
    CP_COMMIT();
}

// Convert 3 float4 (96x32 A chunk slice per thread) and store hi/lo.
__device__ __forceinline__ void store_a(const float4 (&ar)[3],
                                        char* ah, char* al, int tid)
{
#pragma unroll
    for (int j = 0; j < 3; j++) {
        int idx = tid + j * NTHR;         // 0..767
        int r  = idx >> 3;                // row 0..95
        int c  = (idx & 7) * 4;           // col (fp32 units, 0..28)
        float4 f = ar[j];
        __half h0 = __float2half_rn(f.x);
        __half h1 = __float2half_rn(f.y);
        __half h2 = __float2half_rn(f.z);
        __half h3 = __float2half_rn(f.w);
        uint32_t hh0 = ((uint32_t)__half_as_ushort(h1) << 16) | __half_as_ushort(h0);
        uint32_t hh1 = ((uint32_t)__half_as_ushort(h3) << 16) | __half_as_ushort(h2);
        __half l0 = __float2half_rn(f.x - __half2float(h0));
        __half l1 = __float2half_rn(f.y - __half2float(h1));
        __half l2 = __float2half_rn(f.z - __half2float(h2));
        __half l3 = __float2half_rn(f.w - __half2float(h3));
        uint32_t ll0 = ((uint32_t)__half_as_ushort(l1) << 16) | __half_as_ushort(l0);
        uint32_t ll1 = ((uint32_t)__half_as_ushort(l3) << 16) | __half_as_ushort(l2);
        int off = r * ASTR + c * 2;
        *(uint2*)(ah + off) = make_uint2(hh0, hh1);
        *(uint2*)(al + off) = make_uint2(ll0, ll1);
    }
}

__device__ __forceinline__ void load_a_chunk(const float* __restrict__ X,
                                             float4 (&ar)[3], int row0, int kt, int tid)
{
#pragma unroll
    for (int j = 0; j < 3; j++) {
        int idx = tid + j * NTHR;
        int r  = idx >> 3;
        int c  = (idx & 7) * 4;
        int rg = row0 + r;
        rg = rg < TOK ? rg : TOK - 1;    // tail clamp
        ar[j] = *(const float4*)(X + (size_t)rg * HH + kt * 32 + c);
    }
}

__global__ __launch_bounds__(NTHR, 2)
void scores_tc_kernel(const float* __restrict__ X,
                      const __half* __restrict__ wh,
                      const __half* __restrict__ wl,
                      const float* __restrict__ bias,
                      const float* __restrict__ v,
                      float* __restrict__ scores)
{
    extern __shared__ char smem[];
    const int tid  = threadIdx.x;
    const int lane = tid & 31;
    const int wid  = tid >> 5;
    const int warp_m = wid & 1;        // 0..1 -> 48-row slab
    const int warp_n = wid >> 1;       // 0..3 -> 32-col slab
    const int row0 = blockIdx.x * BM;

    const uint32_t sb = smem_u32(smem);
    float* sv  = (float*)(smem + OFF_V);
    float* sbi = (float*)(smem + OFF_BI);
    for (int i = tid; i < HH; i += NTHR) { sv[i] = v[i]; sbi[i] = bias[i]; }

    // Prefetch first B tile (it = 0 -> buf 0).
    issue_b(wh, wl, sb + OFF_B, 0, 0, tid);

    // Prologue: A chunk kt=0 -> stage 0.
    {
        float4 ar[3];
        load_a_chunk(X, ar, row0, 0, tid);
        store_a(ar, smem + OFF_A, smem + OFF_A + A_PLANE, tid);
    }

    // ldmatrix lane offsets (bytes)
    const int a_off = (warp_m * 48 + (lane & 15)) * ASTR + ((lane >> 4) << 4);
    const int b_off = (warp_n * 32 + (lane & 7) + ((lane >> 4) << 3)) * ASTR
                    + (((lane >> 3) & 1) << 4);

    float sacc[6] = {0.f, 0.f, 0.f, 0.f, 0.f, 0.f};   // [mi*2 + half]

    for (int nc = 0; nc < 4; nc++) {
        float acc[3][4][4];
        uint32_t corr[3][4][2];
#pragma unroll
        for (int mi = 0; mi < 3; mi++)
#pragma unroll
            for (int ni = 0; ni < 4; ni++) {
#pragma unroll
                for (int c = 0; c < 4; c++) acc[mi][ni][c] = 0.f;
                corr[mi][ni][0] = 0u; corr[mi][ni][1] = 0u;
            }

        for (int kt = 0; kt < 16; kt++) {
            const int it = nc * 16 + kt;
            const int buf = it & 1;
            const bool have_next = (it < 63);

            CP_WAIT0();
            __syncthreads();        // A+B stage(kt) ready; prev stages free

            if (have_next) {
                int nit = it + 1;
                issue_b(wh, wl, sb + OFF_B + (buf ^ 1) * B_STAGE,
                        nit >> 4, nit & 15, tid);
            }

            // Prefetch next A chunk (fp32) into regs; latency hidden by MMAs.
            float4 ar[3];
            if (have_next) load_a_chunk(X, ar, row0, (kt + 1) & 15, tid);

            const uint32_t ah_base = sb + OFF_A + buf * A_STAGE + a_off;
            const uint32_t al_base = ah_base + A_PLANE;
            const uint32_t bh_b = sb + OFF_B + buf * B_STAGE + b_off;
            const uint32_t bl_b = bh_b + B_PLANE;

#pragma unroll
            for (int k16 = 0; k16 < 2; k16++) {
                const int ko = k16 * 32;
                uint32_t ah0[4], ah1[4], ah2[4], al0[4], al1[4], al2[4];
                ldsm4(ah0, ah_base + ko);
                ldsm4(ah1, ah_base + 1280 + ko);    // +16 rows
                ldsm4(ah2, ah_base + 2560 + ko);    // +32 rows
                ldsm4(al0, al_base + ko);
                ldsm4(al1, al_base + 1280 + ko);
                ldsm4(al2, al_base + 2560 + ko);
#pragma unroll
                for (int np = 0; np < 2; np++) {
                    const int bo = np * 1280 + ko;
                    uint32_t bh[4], bl[4];
                    ldsm4(bh, bh_b + bo);
                    ldsm4(bl, bl_b + bo);
                    // main terms: fp32 accumulate
                    mma_f32(acc[0][2 * np],     ah0, bh[0], bh[1]);
                    mma_f32(acc[0][2 * np + 1], ah0, bh[2], bh[3]);
                    mma_f32(acc[1][2 * np],     ah1, bh[0], bh[1]);
                    mma_f32(acc[1][2 * np + 1], ah1, bh[2], bh[3]);
                    mma_f32(acc[2][2 * np],     ah2, bh[0], bh[1]);
                    mma_f32(acc[2][2 * np + 1], ah2, bh[2], bh[3]);
                    // corrections: fp16 accumulate; RAW pairs spaced.
                    mma_f16(corr[0][2 * np],     ah0, bl[0], bl[1]);
                    mma_f16(corr[0][2 * np + 1], ah0, bl[2], bl[3]);
                    mma_f16(corr[1][2 * np],     ah1, bl[0], bl[1]);
                    mma_f16(corr[1][2 * np + 1], ah1, bl[2], bl[3]);
                    mma_f16(corr[2][2 * np],     ah2, bl[0], bl[1]);
                    mma_f16(corr[2][2 * np + 1], ah2, bl[2], bl[3]);
                    mma_f16(corr[0][2 * np],     al0, bh[0], bh[1]);
                    mma_f16(corr[0][2 * np + 1], al0, bh[2], bh[3]);
                    mma_f16(corr[1][2 * np],     al1, bh[0], bh[1]);
                    mma_f16(corr[1][2 * np + 1], al1, bh[2], bh[3]);
                    mma_f16(corr[2][2 * np],     al2, bh[0], bh[1]);
                    mma_f16(corr[2][2 * np + 1], al2, bh[2], bh[3]);
                }
            }

            // Convert + store next A chunk into the other stage.
            if (have_next) {
                char* ahd = smem + OFF_A + (buf ^ 1) * A_STAGE;
                store_a(ar, ahd, ahd + A_PLANE, tid);
            }
        }

        // fused partial epilogue for this 128-col chunk
#pragma unroll
        for (int mi = 0; mi < 3; mi++)
#pragma unroll
            for (int ni = 0; ni < 4; ni++) {
                float2 c01 = __half22float2(*(const __half2*)&corr[mi][ni][0]);
                float2 c23 = __half22float2(*(const __half2*)&corr[mi][ni][1]);
                float cf[4] = {c01.x, c01.y, c23.x, c23.y};
#pragma unroll
                for (int c = 0; c < 4; c++) {
                    int n = nc * 128 + warp_n * 32 + ni * 8 + (lane & 3) * 2 + (c & 1);
                    float t = fast_tanh(acc[mi][ni][c] + cf[c] + sbi[n]);
                    sacc[mi * 2 + (c >> 1)] = fmaf(sv[n], t, sacc[mi * 2 + (c >> 1)]);
                }
            }
    }

    // cross-warp reduction: red[96][16] aliases the (dead) B ring.
    float* red = (float*)(smem + OFF_RED);
    __syncthreads();   // all B/A reads done before aliasing
#pragma unroll
    for (int mi = 0; mi < 3; mi++)
#pragma unroll
        for (int half = 0; half < 2; half++) {
            int m = warp_m * 48 + mi * 16 + half * 8 + (lane >> 2);
            red[m * 16 + warp_n * 4 + (lane & 3)] = sacc[mi * 2 + half];
        }
    __syncthreads();
    if (tid < BM) {
        float s = 0.f;
#pragma unroll
        for (int j = 0; j < 16; j++) s += red[tid * 16 + j];
        if (row0 + tid < TOK) scores[row0 + tid] = s;
    }
}

// ---------------------------------------------------------------------------
// Mask dtype detection: numpy bool may be serialized as int32 or uint8.
// ---------------------------------------------------------------------------
__global__ void detect_mask_kernel(const unsigned* __restrict__ mask_words)
{
    if (threadIdx.x == 0) {
        int ok = 1;
        for (int i = 0; i < 256; i++) {
            if (mask_words[i] > 1u) { ok = 0; break; }
        }
        g_mask_is_i32 = ok;
    }
}

// ---------------------------------------------------------------------------
// Masked softmax over S per batch row.
// ---------------------------------------------------------------------------
__global__ __launch_bounds__(256)
void softmax_kernel(const float* __restrict__ scores,
                    const void* __restrict__ mask,
                    float* __restrict__ attn)
{
    const int b = blockIdx.x;
    const int tid = threadIdx.x;
    __shared__ float sred[256];
    __shared__ int s_is_i32;

    if (tid == 0) s_is_i32 = g_mask_is_i32;
    __syncthreads();
    const int is_i32 = s_is_i32;

    const int* mi = (const int*)mask;
    const unsigned char* mu = (const unsigned char*)mask;

    float vals[8];
    float mx = -INFINITY;
#pragma unroll
    for (int j = 0; j < 8; j++) {
        int idx = b * SS + tid + j * 256;
        float sc = scores[idx];
        bool m = is_i32 ? (mi[idx] != 0) : (mu[idx] != 0);
        sc = m ? sc : NEGV;
        vals[j] = sc;
        mx = fmaxf(mx, sc);
    }
    sred[tid] = mx; __syncthreads();
    for (int off = 128; off > 0; off >>= 1) {
        if (tid < off) sred[tid] = fmaxf(sred[tid], sred[tid + off]);
        __syncthreads();
    }
    mx = sred[0]; __syncthreads();

    float sum = 0.f;
#pragma unroll
    for (int j = 0; j < 8; j++) {
        vals[j] = expf(vals[j] - mx);
        sum += vals[j];
    }
    sred[tid] = sum; __syncthreads();
    for (int off = 128; off > 0; off >>= 1) {
        if (tid < off) sred[tid] += sred[tid + off];
        __syncthreads();
    }
    sum = sred[0];

    float inv = 1.f / sum;
#pragma unroll
    for (int j = 0; j < 8; j++) {
        attn[b * SS + tid + j * 256] = vals[j] * inv;
    }
}

// ---------------------------------------------------------------------------
// weighted_output[b,h] = sum_s attn[b,s] * X[b,s,h]
// Stage 1: S split 8 ways -> partials (grid 64x4x8). Stage 2: reduce.
// ---------------------------------------------------------------------------
__global__ __launch_bounds__(128)
void weighted_part_kernel(const float* __restrict__ X,
                          const float* __restrict__ attn,
                          float* __restrict__ part)
{
    const int b  = blockIdx.x;
    const int h  = blockIdx.y * 128 + threadIdx.x;
    const int sc = blockIdx.z;              // 0..7, 256 s each
    const int s0 = sc * 256;
    const float* xb = X + (size_t)b * SS * HH + (size_t)s0 * HH + h;
    const float* ab = attn + b * SS + s0;

    float a0 = 0.f, a1 = 0.f, a2 = 0.f, a3 = 0.f;
#pragma unroll 4
    for (int s = 0; s < 256; s += 4) {
        a0 = fmaf(__ldg(&ab[s + 0]), __ldg(&xb[(size_t)(s + 0) * HH]), a0);
        a1 = fmaf(__ldg(&ab[s + 1]), __ldg(&xb[(size_t)(s + 1) * HH]), a1);
        a2 = fmaf(__ldg(&ab[s + 2]), __ldg(&xb[(size_t)(s + 2) * HH]), a2);
        a3 = fmaf(__ldg(&ab[s + 3]), __ldg(&xb[(size_t)(s + 3) * HH]), a3);
    }
    part[((size_t)sc * BB + b) * HH + h] = (a0 + a1) + (a2 + a3);
}

__global__ __launch_bounds__(256)
void weighted_reduce_kernel(const float* __restrict__ part,
                            float* __restrict__ out)
{
    int idx = blockIdx.x * 256 + threadIdx.x;   // BB*HH = 32768
    float s = 0.f;
#pragma unroll
    for (int j = 0; j < 8; j++) s += part[j * BB * HH + idx];
    out[idx] = s;
}

// ---------------------------------------------------------------------------
extern "C" void kernel_launch(void* const* d_in, const int* in_sizes, int n_in,
                              void* d_out, int out_size)
{
    const float* X    = (const float*)d_in[0];   // [B,S,H]
    const void*  mask = d_in[1];                 // [B,S] bool (int32 or uint8)
    const float* W    = (const float*)d_in[2];   // [H,H]
    const float* bias = (const float*)d_in[3];   // [H]
    const float* v    = (const float*)d_in[4];   // [H]
    float* out = (float*)d_out;

    // Output layout: weighted_output [B,H] first, attn_weights [B,S] second.
    float* attn;
    if (out_size >= BB * HH + TOK) {
        attn = out + BB * HH;
    } else {
        void* p = nullptr;
        cudaGetSymbolAddress(&p, g_attn_fallback);
        attn = (float*)p;
    }
    void* sp = nullptr; cudaGetSymbolAddress(&sp, g_scores);
    float* scores = (float*)sp;
    void* pp = nullptr; cudaGetSymbolAddress(&pp, g_part);
    float* part = (float*)pp;
    void* whp = nullptr; cudaGetSymbolAddress(&whp, g_wh);
    void* wlp = nullptr; cudaGetSymbolAddress(&wlp, g_wl);
    __half* wh = (__half*)whp;
    __half* wl = (__half*)wlp;

    cudaFuncSetAttribute(scores_tc_kernel,
                         cudaFuncAttributeMaxDynamicSharedMemorySize, SMEM_TOTAL);

    detect_mask_kernel<<<1, 32>>>((const unsigned*)mask);   // idx 0
    wsplit_kernel<<<HH * HH / 1024, 256>>>(W, wh, wl);      // idx 1
    dummy_kernel<<<1, 32>>>();                              // idx 2 (ncu slot shim)
    scores_tc_kernel<<<GRID_M, NTHR, SMEM_TOTAL>>>(X, wh, wl, bias, v, scores); // idx 3
    softmax_kernel<<<BB, 256>>>(scores, mask, attn);
    weighted_part_kernel<<<dim3(BB, HH / 128, 8), 128>>>(X, attn, part);
    weighted_reduce_kernel<<<BB * HH / 256, 256>>>(part, out);
}